// round 14
// baseline (speedup 1.0000x reference)
#include <cuda_runtime.h>
#include <cuda_fp16.h>
#include <cstdint>

// Shapes (fixed by the problem)
#define B_  64
#define T_  512
#define D_  768
#define L_  31
#define LL_ 961
#define NTOK (B_*T_)      // 32768
#define IDX_EOS 29
#define IDX_BOS 30

// Scratch (static __device__, no allocation)
__device__ float g_outs[NTOK * L_];   // out_s (post bias + mask adjust)
__device__ float g_eos [NTOK * L_];   // exp(out_s)
// packed f16x2 weight pairs (k-adjacent), pre-shuffled to the smem layout:
// chunk c (24 chunks of 32 k), word (kp 0..15, n 0..31) at
//   c*640 + kp*40 + (n&7)*4 + (n>>3)     [words 32..39 of each kp row = pad]
// values prescaled by 4096 (exact power of 2).
__device__ __align__(16) unsigned g_wph[24 * 640];
__device__ __align__(16) unsigned g_wpl[24 * 640];

__device__ __forceinline__ void mma16(float& c0, float& c1, float& c2, float& c3,
    unsigned a0, unsigned a1, unsigned a2, unsigned a3, unsigned b0, unsigned b1)
{
    asm("mma.sync.aligned.m16n8k16.row.col.f32.f16.f16.f32 "
        "{%0,%1,%2,%3}, {%4,%5,%6,%7}, {%8,%9}, {%0,%1,%2,%3};"
        : "+f"(c0), "+f"(c1), "+f"(c2), "+f"(c3)
        : "r"(a0), "r"(a1), "r"(a2), "r"(a3), "r"(b0), "r"(b1));
}

__device__ __forceinline__ void split16(float2 f, unsigned& h, unsigned& l)
{
    float sx = f.x * 16.f, sy = f.y * 16.f;
    __half2 hh = __floats2half2_rn(sx, sy);
    float2 hf = __half22float2(hh);
    __half2 ll = __floats2half2_rn(sx - hf.x, sy - hf.y);
    h = *(unsigned*)&hh;
    l = *(unsigned*)&ll;
}

__device__ __forceinline__ unsigned s2u(const void* p) {
    return (unsigned)__cvta_generic_to_shared(p);
}
__device__ __forceinline__ void cp16(unsigned dst, const void* src) {
    asm volatile("cp.async.cg.shared.global [%0], [%1], 16;"
                 :: "r"(dst), "l"(src));
}

// ---------------------------------------------------------------------------
// Kernel 0: pack state_w into f16 hi/lo pairs, prescaled x4096, shuffled layout.
// ---------------------------------------------------------------------------
__global__ __launch_bounds__(256) void prep_w(const float* __restrict__ w)
{
    int i = blockIdx.x * 256 + threadIdx.x;
    if (i >= 24 * 640) return;
    int c  = i / 640, r = i - c * 640;
    int kp = r / 40,  wd = r - kp * 40;
    unsigned hi = 0, lo = 0;
    if (wd < 32) {
        int t4 = wd & 3, g = wd >> 2;
        int n  = t4 * 8 + g;
        int k0 = c * 32 + kp * 2;
        float v0 = (n < L_) ? __ldg(&w[n * D_ + k0])     * 4096.f : 0.f;
        float v1 = (n < L_) ? __ldg(&w[n * D_ + k0 + 1]) * 4096.f : 0.f;
        __half2 h = __floats2half2_rn(v0, v1);
        float2 hf = __half22float2(h);
        __half2 l = __floats2half2_rn(v0 - hf.x, v1 - hf.y);
        hi = *(unsigned*)&h;
        lo = *(unsigned*)&l;
    }
    g_wph[i] = hi;
    g_wpl[i] = lo;
}

// ---------------------------------------------------------------------------
// Kernel 1: f16 double-split GEMM, split-K two-group version.
// 256 threads = 2 groups x 4 warps. Group g streams k-chunks [g*12, g*12+12)
// via cp.async double-buffer + per-group named barriers; same 64x32 tile.
// End: group1 c -> smem, group0 adds, epilogue.
// Dynamic smem layout (floats), per group (stride 7680):
//   [0,5120)     sA  2 buffers of 64x40
//   [5120,6400)  sBh 2 buffers of 640 words
//   [6400,7680)  sBl 2 buffers of 640 words
// ---------------------------------------------------------------------------
#define GCH 12          // chunks per group
#define GSTR 7680       // group smem stride (floats)
#define SMEMB (2 * GSTR * 4)   // 61440 bytes

__global__ __launch_bounds__(256) void gemm_kernel(
    const float* __restrict__ input,
    const float* __restrict__ state_b,
    const float* __restrict__ mask)
{
    extern __shared__ __align__(16) float dyn[];

    const int tid  = threadIdx.x;
    const int lane = tid & 31;
    const int gid  = tid >> 7;          // group 0/1
    const int gtid = tid & 127;
    const int w4   = (tid >> 5) & 3;    // warp within group
    const int g    = lane >> 2, q = lane & 3;
    const int tokbase = blockIdx.x * 64;

    float* gbase = dyn + gid * GSTR;
    float*    sA0 = gbase;
    unsigned* sBh0 = (unsigned*)(gbase + 5120);
    unsigned* sBl0 = (unsigned*)(gbase + 6400);

    float c[4][4];
#pragma unroll
    for (int t4 = 0; t4 < 4; t4++)
#pragma unroll
        for (int u = 0; u < 4; u++) c[t4][u] = 0.f;

    auto loadc = [&](int ch, int buf) {
        const int k0 = gid * 384 + ch * 32;
        float* sA = sA0 + buf * 2560;
#pragma unroll
        for (int i = 0; i < 4; i++) {
            int idx = gtid + 128 * i; int row = idx >> 3, c4 = idx & 7;
            cp16(s2u(sA + row * 40 + c4 * 4),
                 input + (size_t)(tokbase + row) * D_ + k0 + c4 * 4);
        }
        const int cb = gid * GCH + ch;
        const uint4* gh = (const uint4*)(g_wph + cb * 640);
        const uint4* gl = (const uint4*)(g_wpl + cb * 640);
        cp16(s2u(sBh0 + buf * 640 + gtid * 4), gh + gtid);
        cp16(s2u(sBl0 + buf * 640 + gtid * 4), gl + gtid);
        if (gtid < 32) {
            cp16(s2u(sBh0 + buf * 640 + (gtid + 128) * 4), gh + gtid + 128);
            cp16(s2u(sBl0 + buf * 640 + (gtid + 128) * 4), gl + gtid + 128);
        }
        asm volatile("cp.async.commit_group;");
    };

    loadc(0, 0);

    const int ar = w4 * 16 + g;
    const int barid = gid + 1;
    for (int ch = 0; ch < GCH; ch++) {
        asm volatile("cp.async.wait_group 0;");
        asm volatile("bar.sync %0, 128;" :: "r"(barid) : "memory");
        if (ch + 1 < GCH) loadc(ch + 1, (ch + 1) & 1);

        const int buf = ch & 1;
        const float*    A  = sA0 + buf * 2560;
        const unsigned* Bh = sBh0 + buf * 640;
        const unsigned* Bl = sBl0 + buf * 640;

#pragma unroll
        for (int kk = 0; kk < 2; kk++) {
            const int K0 = kk * 16 + 2 * q;
            float2 f00 = *(const float2*)&A[ar * 40 + K0];
            float2 f01 = *(const float2*)&A[(ar + 8) * 40 + K0];
            float2 f10 = *(const float2*)&A[ar * 40 + K0 + 8];
            float2 f11 = *(const float2*)&A[(ar + 8) * 40 + K0 + 8];

            unsigned ah0, ah1, ah2, ah3, al0, al1, al2, al3;
            split16(f00, ah0, al0);
            split16(f01, ah1, al1);
            split16(f10, ah2, al2);
            split16(f11, ah3, al3);

            const int b0i = (kk * 8 + q) * 40 + g * 4;
            uint4 B0h = *(const uint4*)&Bh[b0i];
            uint4 B1h = *(const uint4*)&Bh[b0i + 160];
            uint4 B0l = *(const uint4*)&Bl[b0i];
            uint4 B1l = *(const uint4*)&Bl[b0i + 160];
            unsigned b0h[4] = {B0h.x, B0h.y, B0h.z, B0h.w};
            unsigned b1h[4] = {B1h.x, B1h.y, B1h.z, B1h.w};
            unsigned b0l[4] = {B0l.x, B0l.y, B0l.z, B0l.w};
            unsigned b1l[4] = {B1l.x, B1l.y, B1l.z, B1l.w};

#pragma unroll
            for (int t4 = 0; t4 < 4; t4++) {
                mma16(c[t4][0], c[t4][1], c[t4][2], c[t4][3],
                      ah0, ah1, ah2, ah3, b0h[t4], b1h[t4]);
                mma16(c[t4][0], c[t4][1], c[t4][2], c[t4][3],
                      ah0, ah1, ah2, ah3, b0l[t4], b1l[t4]);
                mma16(c[t4][0], c[t4][1], c[t4][2], c[t4][3],
                      al0, al1, al2, al3, b0h[t4], b1h[t4]);
            }
        }
    }

    // ---- cross-group reduction: group1 -> smem, group0 adds ----
    __syncthreads();
    float* red = dyn + GSTR;              // group1 region (dead now)
    if (gid == 1) {
        const int base = (w4 * 32 + lane) * 16;
#pragma unroll
        for (int t4 = 0; t4 < 4; t4++)
#pragma unroll
            for (int u = 0; u < 4; u++) red[base + t4 * 4 + u] = c[t4][u];
    }
    __syncthreads();

    float* outs = dyn;                    // 64 x 32, pitch 32 (group0 region)
    if (gid == 0) {
        const int base = (w4 * 32 + lane) * 16;
#pragma unroll
        for (int t4 = 0; t4 < 4; t4++)
#pragma unroll
            for (int u = 0; u < 4; u++) c[t4][u] += red[base + t4 * 4 + u];

        const float INV = 1.52587890625e-05f;   // 2^-16, exact
        const int r0 = w4 * 16 + g;
        const int jb = 2 * q;
        const float mk0 = __ldg(&mask[tokbase + r0]);
        const float mk1 = __ldg(&mask[tokbase + r0 + 8]);
#pragma unroll
        for (int t4 = 0; t4 < 4; t4++) {
            const int j0 = t4 * 8 + jb;
            float bb = __ldg(&state_b[j0]);
            float v00 = c[t4][0] * INV + bb, v10 = c[t4][2] * INV + bb;
            if (j0 == IDX_EOS) { v00 += (mk0 == 0.f) ? 2e4f : 0.f;
                                 v10 += (mk1 == 0.f) ? 2e4f : 0.f; }
            outs[r0 * 32 + j0]       = v00;
            outs[(r0 + 8) * 32 + j0] = v10;
            const int j1 = j0 + 1;
            if (j1 < L_) {
                float bb1 = __ldg(&state_b[j1]);
                float v01 = c[t4][1] * INV + bb1, v11 = c[t4][3] * INV + bb1;
                if (j1 == IDX_EOS) { v01 += (mk0 == 0.f) ? 2e4f : 0.f;
                                     v11 += (mk1 == 0.f) ? 2e4f : 0.f; }
                outs[r0 * 32 + j1]       = v01;
                outs[(r0 + 8) * 32 + j1] = v11;
            }
        }
    }
    __syncthreads();

    // ---- g_outs / g_eos (all 256 threads) ----
    for (int i = tid; i < 64 * L_; i += 256) {
        int tok = i / L_;
        int j   = i - tok * L_;
        float v = outs[tok * 32 + j];
        size_t gi = (size_t)(tokbase + tok) * L_ + j;
        g_outs[gi] = v;
        g_eos [gi] = __expf(v);
    }
}

// ---------------------------------------------------------------------------
// Scan pieces (R11/R12, measured good): forward/backward split, one warp/batch.
// ---------------------------------------------------------------------------
#define SHF(x, s) __shfl_sync(0xffffffffu, x, s)

__device__ __forceinline__ void stepFB(float& p, float& v,
    int f0, int f1, int b0, int b1,
    const float (&wF)[16], const float (&wB)[16], float eF, float eB)
{
    float g = eB * v;
    float a0 = wF[0] * SHF(p, f0);
    float a1 = wF[1] * SHF(p, f1);
    float c0 = wB[0] * SHF(g, b0);
    float c1 = wB[1] * SHF(g, b1);
    float a2 = wF[2] * SHF(p, 6);
    float a3 = wF[3] * SHF(p, 7);
    float c2 = wB[2] * SHF(g, 4);
    float c3 = wB[3] * SHF(g, 7);
    a0 = fmaf(wF[4],  SHF(p, 10), a0);  c0 = fmaf(wB[4],  SHF(g, 8),  c0);
    a1 = fmaf(wF[5],  SHF(p, 11), a1);  c1 = fmaf(wB[5],  SHF(g, 11), c1);
    a2 = fmaf(wF[6],  SHF(p, 14), a2);  c2 = fmaf(wB[6],  SHF(g, 12), c2);
    a3 = fmaf(wF[7],  SHF(p, 15), a3);  c3 = fmaf(wB[7],  SHF(g, 15), c3);
    a0 = fmaf(wF[8],  SHF(p, 18), a0);  c0 = fmaf(wB[8],  SHF(g, 16), c0);
    a1 = fmaf(wF[9],  SHF(p, 19), a1);  c1 = fmaf(wB[9],  SHF(g, 19), c1);
    a2 = fmaf(wF[10], SHF(p, 22), a2);  c2 = fmaf(wB[10], SHF(g, 20), c2);
    a3 = fmaf(wF[11], SHF(p, 23), a3);  c3 = fmaf(wB[11], SHF(g, 23), c3);
    a0 = fmaf(wF[12], SHF(p, 26), a0);  c0 = fmaf(wB[12], SHF(g, 24), c0);
    a1 = fmaf(wF[13], SHF(p, 27), a1);  c1 = fmaf(wB[13], SHF(g, 27), c1);
    a2 = fmaf(wF[14], SHF(p, 28), a2);  c2 = fmaf(wB[14], SHF(g, 28), c2);
    a3 = fmaf(wF[15], SHF(p, 29), a3);  c3 = fmaf(wB[15], SHF(g, 29), c3);
    p = ((a0 + a1) + (a2 + a3)) * eF;
    v = (c0 + c1) + (c2 + c3);
}

__device__ __forceinline__ void stepB(float& v, int b0, int b1,
                                      const float (&wB)[16], float eB)
{
    float g = eB * v;
    float c0 = wB[0] * SHF(g, b0);
    float c1 = wB[1] * SHF(g, b1);
    float c2 = wB[2] * SHF(g, 4);
    float c3 = wB[3] * SHF(g, 7);
    c0 = fmaf(wB[4],  SHF(g, 8),  c0);
    c1 = fmaf(wB[5],  SHF(g, 11), c1);
    c2 = fmaf(wB[6],  SHF(g, 12), c2);
    c3 = fmaf(wB[7],  SHF(g, 15), c3);
    c0 = fmaf(wB[8],  SHF(g, 16), c0);
    c1 = fmaf(wB[9],  SHF(g, 19), c1);
    c2 = fmaf(wB[10], SHF(g, 20), c2);
    c3 = fmaf(wB[11], SHF(g, 23), c3);
    c0 = fmaf(wB[12], SHF(g, 24), c0);
    c1 = fmaf(wB[13], SHF(g, 27), c1);
    c2 = fmaf(wB[14], SHF(g, 28), c2);
    c3 = fmaf(wB[15], SHF(g, 29), c3);
    v = (c0 + c1) + (c2 + c3);
}

__device__ void scan_body(
    int b, int j,
    const float* __restrict__ trans,
    const int* __restrict__ target32,
    float* __restrict__ loss)
{
    const bool act = (j < L_);
    const int jc = min(j, 30);
    const float* eb = g_eos + (size_t)b * T_ * L_;

    bool is64 = true;
#pragma unroll
    for (int qd = 0; qd < 64; qd++) is64 &= (__ldg(&target32[2 * qd + 1]) == 0);
    const int tstride = is64 ? 2 : 1;

    const bool lightF = (j < 28) && (((j & 3) == 1) || ((j & 3) == 2));
    const int f0 = lightF ? (j & ~3) : 2;
    const int f1 = f0 + 1;

    float wF[16];
    {
        int src[16];
        src[0] = f0; src[1] = f1;
#pragma unroll
        for (int k = 1; k < 7; k++) { src[2*k] = 4*k + 2; src[2*k+1] = 4*k + 3; }
        src[14] = 28; src[15] = 29;
#pragma unroll
        for (int k = 0; k < 16; k++)
            wF[k] = act ? __expf(__ldg(&trans[src[k] * L_ + j])) : 0.f;
    }

    int b0, b1;
    if (j < 28 && (j & 3) == 0)      { b0 = j + 1; b1 = j + 2; }
    else if (j < 28 && (j & 3) == 1) { b0 = j;     b1 = j + 1; }
    else if (j == 29)                { b0 = 29;    b1 = 30;    }
    else                             { b0 = 0;     b1 = 3;     }

    float wB[16];
    {
        int src[16];
        src[0] = b0; src[1] = b1;
        src[2] = 4;  src[3] = 7;  src[4] = 8;  src[5] = 11;
        src[6] = 12; src[7] = 15; src[8] = 16; src[9] = 19;
        src[10] = 20; src[11] = 23; src[12] = 24; src[13] = 27;
        src[14] = 28; src[15] = 29;
#pragma unroll
        for (int k = 0; k < 16; k++)
            wB[k] = act ? __expf(__ldg(&trans[jc * L_ + src[k]])) : 0.f;
    }

    float p = act ? __expf(__ldg(&trans[IDX_BOS * L_ + j])) * __ldg(&eb[j]) : 0.f;
    float v = act ? __expf(__ldg(&trans[jc * L_ + IDX_EOS])) : 0.f;
    int esF = 0, esB = 0;

    float e0F[8], e1F[8], e0B[8], e1B[8];
#pragma unroll
    for (int u = 0; u < 7; u++) e0F[u] = act ? eb[(1 + u) * L_ + j] : 0.f;
#pragma unroll
    for (int u = 0; u < 8; u++) {
        e0B[u] = act ? eb[(511 - u) * L_ + j] : 0.f;
        e1F[u] = act ? eb[(8 + u) * L_ + j] : 0.f;
        e1B[u] = act ? eb[(503 - u) * L_ + j] : 0.f;
    }

    stepB(v, b0, b1, wB, e0B[0]);
#pragma unroll
    for (int u = 0; u < 7; u++)
        stepFB(p, v, f0, f1, b0, b1, wF, wB, e0F[u], e0B[u + 1]);
    {
        unsigned mF = __reduce_max_sync(0xffffffffu, __float_as_uint(p));
        unsigned mB = __reduce_max_sync(0xffffffffu, __float_as_uint(v));
        int eF = (int)(mF >> 23), eB = (int)(mB >> 23);
        p *= __uint_as_float((unsigned)(253 - eF) << 23);
        v *= __uint_as_float((unsigned)(253 - eB) << 23);
        esF += eF - 126; esB += eB - 126;
    }

#pragma unroll 1
    for (int o = 1; o < 32; o++) {
#pragma unroll
        for (int u = 0; u < 8; u++) { e0F[u] = e1F[u]; e0B[u] = e1B[u]; }
        if (o < 31) {
            const int tf = 8 * (o + 1);
            const int tbk = 503 - 8 * o;
#pragma unroll
            for (int u = 0; u < 8; u++) {
                e1F[u] = act ? eb[(tf + u) * L_ + j] : 0.f;
                e1B[u] = act ? eb[(tbk - u) * L_ + j] : 0.f;
            }
        }
#pragma unroll
        for (int u = 0; u < 8; u++)
            stepFB(p, v, f0, f1, b0, b1, wF, wB, e0F[u], e0B[u]);
        unsigned mF = __reduce_max_sync(0xffffffffu, __float_as_uint(p));
        unsigned mB = __reduce_max_sync(0xffffffffu, __float_as_uint(v));
        int eF = (int)(mF >> 23), eB = (int)(mB >> 23);
        p *= __uint_as_float((unsigned)(253 - eF) << 23);
        v *= __uint_as_float((unsigned)(253 - eB) << 23);
        esF += eF - 126; esB += eB - 126;
    }

    const size_t tb = (size_t)b * T_;
    float ts = 0.f;
    for (int t = j; t < T_; t += 32) {
        int tgt  = __ldg(&target32[(tb + t) * tstride]);
        int prev = (t == 0) ? IDX_BOS : __ldg(&target32[(tb + t - 1) * tstride]);
        tgt  = min(max(tgt,  0), L_ - 1);
        prev = min(max(prev, 0), L_ - 1);
        ts += __ldg(&trans[prev * L_ + tgt]) + __ldg(&g_outs[(tb + t) * L_ + tgt]);
    }
#pragma unroll
    for (int s = 16; s; s >>= 1) ts += __shfl_xor_sync(0xffffffffu, ts, s);

    float z = p * v;
#pragma unroll
    for (int s = 16; s; s >>= 1) z += __shfl_xor_sync(0xffffffffu, z, s);

    if (j == 0) {
        const float LN2 = 0.6931471805599453f;
        loss[b] = (float)(esF + esB) * LN2 + __logf(z) - ts;
    }
}

// ---------------------------------------------------------------------------
// Kernel 2: fused scan (blocks 0..63, warp 0 only) + energy write
// (blocks 64..64+1023) — byte-identical to R12/R13 (measured good).
// ---------------------------------------------------------------------------
#define SCANB 64
#define ENERB 1024
#define NGRP  (NTOK / 4)   // 8192 = 1024 * 8

__global__ __launch_bounds__(256) void fused2(
    const float* __restrict__ trans,
    const int* __restrict__ target32,
    float* __restrict__ loss,
    float* __restrict__ energy)
{
    if (blockIdx.x < SCANB) {
        if (threadIdx.x < 32)
            scan_body(blockIdx.x, threadIdx.x, trans, target32, loss);
        return;
    }

    __shared__ float strans[LL_];
    const int tid = threadIdx.x;
    for (int i = tid; i < LL_; i += 256) strans[i] = __ldg(&trans[i]);
    __syncthreads();

    int pr0[4], pko[4];
#pragma unroll
    for (int s = 0; s < 4; s++) {
        int v  = tid + 256 * s;
        if (v > 960) { pr0[s] = 0; pko[s] = 0; continue; }
        int ff = 4 * v;
        int t0 = ff / 961;
        pr0[s] = ff - t0 * 961;
        int oj = 0;
#pragma unroll
        for (int u = 0; u < 4; u++) {
            int fu = ff + u;
            int tl = fu / 961;
            int r  = fu - tl * 961;
            int j  = r % 31;
            oj |= ((tl * 31 + j) & 255) << (8 * u);
        }
        pko[s] = oj;
    }
    const bool has3 = (tid + 768 <= 960);

    float4* e4 = (float4*)energy;
    int g = (int)blockIdx.x - SCANB;
#pragma unroll 1
    for (int it = 0; it < NGRP / ENERB; it++, g += ENERB) {
        const float* ob = g_outs + (size_t)g * 124;   // 4 tokens * 31
        const size_t base4 = (size_t)g * 961;
#pragma unroll
        for (int s = 0; s < 4; s++) {
            if (s == 3 && !has3) break;
            int v = tid + 256 * s;
            int r = pr0[s], oj = pko[s];
            float4 o;
            o.x = strans[r] + __ldg(&ob[oj & 127]);
            int r1 = r + 1; if (r1 >= 961) r1 -= 961;
            o.y = strans[r1] + __ldg(&ob[(oj >> 8) & 127]);
            int r2 = r + 2; if (r2 >= 961) r2 -= 961;
            o.z = strans[r2] + __ldg(&ob[(oj >> 16) & 127]);
            int r3 = r + 3; if (r3 >= 961) r3 -= 961;
            o.w = strans[r3] + __ldg(&ob[(oj >> 24) & 127]);
            e4[base4 + v] = o;
        }
    }
}

// ---------------------------------------------------------------------------
extern "C" void kernel_launch(void* const* d_in, const int* in_sizes, int n_in,
                              void* d_out, int out_size)
{
    const float* input   = (const float*)d_in[0];
    const int*   target  = (const int*)d_in[1];   // int32 or int64 (auto-detected)
    const float* mask    = (const float*)d_in[2];
    const float* state_w = (const float*)d_in[3];
    const float* state_b = (const float*)d_in[4];
    const float* trans   = (const float*)d_in[5];

    float* out    = (float*)d_out;
    float* loss   = out;            // 64 floats
    float* energy = out + B_;       // B*T*31*31 floats (offset 256B, 16B aligned)

    cudaFuncSetAttribute(gemm_kernel,
                         cudaFuncAttributeMaxDynamicSharedMemorySize, SMEMB);

    prep_w<<<60, 256>>>(state_w);
    gemm_kernel<<<NTOK / 64, 256, SMEMB>>>(input, state_b, mask);
    fused2<<<SCANB + ENERB, 256>>>(trans, target, loss, energy);
}

// round 15
// speedup vs baseline: 1.1444x; 1.1444x over previous
#include <cuda_runtime.h>
#include <cuda_fp16.h>
#include <cstdint>

// Shapes (fixed by the problem)
#define B_  64
#define T_  512
#define D_  768
#define L_  31
#define LL_ 961
#define NTOK (B_*T_)      // 32768
#define IDX_EOS 29
#define IDX_BOS 30

// Scratch (static __device__, no allocation)
__device__ float g_outs[NTOK * L_];   // out_s (post bias + mask adjust)
__device__ float g_eos [NTOK * L_];   // exp(out_s)
// packed f16x2 weight pairs (k-adjacent), pre-shuffled to the smem layout:
// chunk c (24 chunks of 32 k), word (kp 0..15, n 0..31) at
//   c*640 + kp*40 + (n&7)*4 + (n>>3)     [words 32..39 of each kp row = pad]
// values prescaled by 4096 (exact power of 2).
__device__ __align__(16) unsigned g_wph[24 * 640];
__device__ __align__(16) unsigned g_wpl[24 * 640];

__device__ __forceinline__ void mma16(float& c0, float& c1, float& c2, float& c3,
    unsigned a0, unsigned a1, unsigned a2, unsigned a3, unsigned b0, unsigned b1)
{
    asm("mma.sync.aligned.m16n8k16.row.col.f32.f16.f16.f32 "
        "{%0,%1,%2,%3}, {%4,%5,%6,%7}, {%8,%9}, {%0,%1,%2,%3};"
        : "+f"(c0), "+f"(c1), "+f"(c2), "+f"(c3)
        : "r"(a0), "r"(a1), "r"(a2), "r"(a3), "r"(b0), "r"(b1));
}

// split a float2 (scaled by 16) into f16x2 hi + f16x2 lo
__device__ __forceinline__ void split16(float2 f, unsigned& h, unsigned& l)
{
    float sx = f.x * 16.f, sy = f.y * 16.f;
    __half2 hh = __floats2half2_rn(sx, sy);
    float2 hf = __half22float2(hh);
    __half2 ll = __floats2half2_rn(sx - hf.x, sy - hf.y);
    h = *(unsigned*)&hh;
    l = *(unsigned*)&ll;
}

// ---------------------------------------------------------------------------
// Kernel 0: pack state_w into f16 hi/lo pairs, prescaled x4096, shuffled layout.
// ---------------------------------------------------------------------------
__global__ __launch_bounds__(256) void prep_w(const float* __restrict__ w)
{
    int i = blockIdx.x * 256 + threadIdx.x;
    if (i >= 24 * 640) return;
    int c  = i / 640, r = i - c * 640;
    int kp = r / 40,  wd = r - kp * 40;
    unsigned hi = 0, lo = 0;
    if (wd < 32) {
        int t4 = wd & 3, g = wd >> 2;
        int n  = t4 * 8 + g;
        int k0 = c * 32 + kp * 2;
        float v0 = (n < L_) ? __ldg(&w[n * D_ + k0])     * 4096.f : 0.f;
        float v1 = (n < L_) ? __ldg(&w[n * D_ + k0 + 1]) * 4096.f : 0.f;
        __half2 h = __floats2half2_rn(v0, v1);
        float2 hf = __half22float2(h);
        __half2 l = __floats2half2_rn(v0 - hf.x, v1 - hf.y);
        hi = *(unsigned*)&h;
        lo = *(unsigned*)&l;
    }
    g_wph[i] = hi;
    g_wpl[i] = lo;
}

// ---------------------------------------------------------------------------
// Kernel 1: f16 double-split GEMM (3 passes: hh, hl, lh), SPLIT-N 8-warp.
// Block: 256 threads (8 warps), tile 64 tokens x 32 labels, k-chunk 32.
// Warp w: rows (w>>1)*16..+15, n-tiles {2*(w&1), 2*(w&1)+1}. No reduction.
// Same smem/dataflow as R13 (register-staged double buffer).
// ---------------------------------------------------------------------------
#define CH  32
#define NCH (D_/CH)   // 24

__global__ __launch_bounds__(256) void gemm_kernel(
    const float* __restrict__ input,
    const float* __restrict__ state_b,
    const float* __restrict__ mask)
{
    __shared__ __align__(16) float    sA [2][64 * 40];
    __shared__ __align__(16) unsigned sBh[2][640];
    __shared__ __align__(16) unsigned sBl[2][640];

    const int tid  = threadIdx.x;
    const int lane = tid & 31, warp = tid >> 5;
    const int g    = lane >> 2, q = lane & 3;
    const int wrow = warp >> 1;          // 0..3 (row group)
    const int np   = warp & 1;           // n-tile pair
    const int tokbase = blockIdx.x * 64;

    float c[2][4];
#pragma unroll
    for (int t4 = 0; t4 < 2; t4++)
#pragma unroll
        for (int u = 0; u < 4; u++) c[t4][u] = 0.f;

    float4 ra[2];
    uint4  rbh, rbl;
    const bool bldr = (tid < 160);

    auto loadg = [&](int ch) {
        const int k0 = ch * CH;
#pragma unroll
        for (int i = 0; i < 2; i++) {
            int idx = tid + 256 * i; int row = idx >> 3, c4 = idx & 7;
            ra[i] = *(const float4*)&input[(size_t)(tokbase + row) * D_ + k0 + c4 * 4];
        }
        if (bldr) {
            rbh = ((const uint4*)(g_wph + ch * 640))[tid];
            rbl = ((const uint4*)(g_wpl + ch * 640))[tid];
        }
    };
    auto stores = [&](int b) {
#pragma unroll
        for (int i = 0; i < 2; i++) {
            int idx = tid + 256 * i; int row = idx >> 3, c4 = idx & 7;
            *(float4*)&sA[b][row * 40 + c4 * 4] = ra[i];
        }
        if (bldr) {
            ((uint4*)sBh[b])[tid] = rbh;
            ((uint4*)sBl[b])[tid] = rbl;
        }
    };

    loadg(0); stores(0); __syncthreads();

    int buf = 0;
    const int ar = wrow * 16 + g;
    for (int ch = 0; ch < NCH; ch++) {
        if (ch + 1 < NCH) loadg(ch + 1);

        const float*    A  = sA [buf];
        const unsigned* Bh = sBh[buf];
        const unsigned* Bl = sBl[buf];

#pragma unroll
        for (int kk = 0; kk < 2; kk++) {
            const int K0 = kk * 16 + 2 * q;
            float2 f00 = *(const float2*)&A[ar * 40 + K0];
            float2 f01 = *(const float2*)&A[(ar + 8) * 40 + K0];
            float2 f10 = *(const float2*)&A[ar * 40 + K0 + 8];
            float2 f11 = *(const float2*)&A[(ar + 8) * 40 + K0 + 8];

            // a-frag order (ldmatrix-canonical): a0=(g,klo) a1=(g+8,klo)
            //                                    a2=(g,khi) a3=(g+8,khi)
            unsigned ah0, ah1, ah2, ah3, al0, al1, al2, al3;
            split16(f00, ah0, al0);
            split16(f01, ah1, al1);
            split16(f10, ah2, al2);
            split16(f11, ah3, al3);

            const int b0i = (kk * 8 + q) * 40 + g * 4 + np * 2;
            uint2 B0h = *(const uint2*)&Bh[b0i];
            uint2 B1h = *(const uint2*)&Bh[b0i + 160];   // kp+4 rows
            uint2 B0l = *(const uint2*)&Bl[b0i];
            uint2 B1l = *(const uint2*)&Bl[b0i + 160];
            unsigned b0h[2] = {B0h.x, B0h.y};
            unsigned b1h[2] = {B1h.x, B1h.y};
            unsigned b0l[2] = {B0l.x, B0l.y};
            unsigned b1l[2] = {B1l.x, B1l.y};

#pragma unroll
            for (int t4 = 0; t4 < 2; t4++) {
                mma16(c[t4][0], c[t4][1], c[t4][2], c[t4][3],
                      ah0, ah1, ah2, ah3, b0h[t4], b1h[t4]);   // hh
                mma16(c[t4][0], c[t4][1], c[t4][2], c[t4][3],
                      ah0, ah1, ah2, ah3, b0l[t4], b1l[t4]);   // hl
                mma16(c[t4][0], c[t4][1], c[t4][2], c[t4][3],
                      al0, al1, al2, al3, b0h[t4], b1h[t4]);   // lh
            }
        }
        __syncthreads();
        if (ch + 1 < NCH) { stores(buf ^ 1); __syncthreads(); }
        buf ^= 1;
    }

    // ---- epilogue: outs tile to smem (overlay on sA, dead now) ----
    const float INV = 1.52587890625e-05f;   // 2^-16, exact
    float* outs = sA[0];                    // 64 x 32, pitch 32
    {
        const int r0 = wrow * 16 + g;
        const int jb = 2 * q;
        const float mk0 = __ldg(&mask[tokbase + r0]);
        const float mk1 = __ldg(&mask[tokbase + r0 + 8]);
#pragma unroll
        for (int t4 = 0; t4 < 2; t4++) {
            const int j0 = (np * 2 + t4) * 8 + jb;
            float bb = __ldg(&state_b[j0]);
            float v00 = c[t4][0] * INV + bb, v10 = c[t4][2] * INV + bb;
            if (j0 == IDX_EOS) { v00 += (mk0 == 0.f) ? 2e4f : 0.f;
                                 v10 += (mk1 == 0.f) ? 2e4f : 0.f; }
            outs[r0 * 32 + j0]       = v00;
            outs[(r0 + 8) * 32 + j0] = v10;
            const int j1 = j0 + 1;
            if (j1 < L_) {
                float bb1 = __ldg(&state_b[j1]);
                float v01 = c[t4][1] * INV + bb1, v11 = c[t4][3] * INV + bb1;
                if (j1 == IDX_EOS) { v01 += (mk0 == 0.f) ? 2e4f : 0.f;
                                     v11 += (mk1 == 0.f) ? 2e4f : 0.f; }
                outs[r0 * 32 + j1]       = v01;
                outs[(r0 + 8) * 32 + j1] = v11;
            }
        }
    }
    __syncthreads();

    // ---- g_outs / g_eos ----
    for (int i = tid; i < 64 * L_; i += 256) {
        int tok = i / L_;
        int j   = i - tok * L_;
        float v = outs[tok * 32 + j];
        size_t gi = (size_t)(tokbase + tok) * L_ + j;
        g_outs[gi] = v;
        g_eos [gi] = __expf(v);
    }
}

// ---------------------------------------------------------------------------
// Scan pieces (R11/R12, measured good): forward/backward split, one warp/batch.
// ---------------------------------------------------------------------------
#define SHF(x, s) __shfl_sync(0xffffffffu, x, s)

__device__ __forceinline__ void stepFB(float& p, float& v,
    int f0, int f1, int b0, int b1,
    const float (&wF)[16], const float (&wB)[16], float eF, float eB)
{
    float g = eB * v;
    float a0 = wF[0] * SHF(p, f0);
    float a1 = wF[1] * SHF(p, f1);
    float c0 = wB[0] * SHF(g, b0);
    float c1 = wB[1] * SHF(g, b1);
    float a2 = wF[2] * SHF(p, 6);
    float a3 = wF[3] * SHF(p, 7);
    float c2 = wB[2] * SHF(g, 4);
    float c3 = wB[3] * SHF(g, 7);
    a0 = fmaf(wF[4],  SHF(p, 10), a0);  c0 = fmaf(wB[4],  SHF(g, 8),  c0);
    a1 = fmaf(wF[5],  SHF(p, 11), a1);  c1 = fmaf(wB[5],  SHF(g, 11), c1);
    a2 = fmaf(wF[6],  SHF(p, 14), a2);  c2 = fmaf(wB[6],  SHF(g, 12), c2);
    a3 = fmaf(wF[7],  SHF(p, 15), a3);  c3 = fmaf(wB[7],  SHF(g, 15), c3);
    a0 = fmaf(wF[8],  SHF(p, 18), a0);  c0 = fmaf(wB[8],  SHF(g, 16), c0);
    a1 = fmaf(wF[9],  SHF(p, 19), a1);  c1 = fmaf(wB[9],  SHF(g, 19), c1);
    a2 = fmaf(wF[10], SHF(p, 22), a2);  c2 = fmaf(wB[10], SHF(g, 20), c2);
    a3 = fmaf(wF[11], SHF(p, 23), a3);  c3 = fmaf(wB[11], SHF(g, 23), c3);
    a0 = fmaf(wF[12], SHF(p, 26), a0);  c0 = fmaf(wB[12], SHF(g, 24), c0);
    a1 = fmaf(wF[13], SHF(p, 27), a1);  c1 = fmaf(wB[13], SHF(g, 27), c1);
    a2 = fmaf(wF[14], SHF(p, 28), a2);  c2 = fmaf(wB[14], SHF(g, 28), c2);
    a3 = fmaf(wF[15], SHF(p, 29), a3);  c3 = fmaf(wB[15], SHF(g, 29), c3);
    p = ((a0 + a1) + (a2 + a3)) * eF;
    v = (c0 + c1) + (c2 + c3);
}

__device__ __forceinline__ void stepB(float& v, int b0, int b1,
                                      const float (&wB)[16], float eB)
{
    float g = eB * v;
    float c0 = wB[0] * SHF(g, b0);
    float c1 = wB[1] * SHF(g, b1);
    float c2 = wB[2] * SHF(g, 4);
    float c3 = wB[3] * SHF(g, 7);
    c0 = fmaf(wB[4],  SHF(g, 8),  c0);
    c1 = fmaf(wB[5],  SHF(g, 11), c1);
    c2 = fmaf(wB[6],  SHF(g, 12), c2);
    c3 = fmaf(wB[7],  SHF(g, 15), c3);
    c0 = fmaf(wB[8],  SHF(g, 16), c0);
    c1 = fmaf(wB[9],  SHF(g, 19), c1);
    c2 = fmaf(wB[10], SHF(g, 20), c2);
    c3 = fmaf(wB[11], SHF(g, 23), c3);
    c0 = fmaf(wB[12], SHF(g, 24), c0);
    c1 = fmaf(wB[13], SHF(g, 27), c1);
    c2 = fmaf(wB[14], SHF(g, 28), c2);
    c3 = fmaf(wB[15], SHF(g, 29), c3);
    v = (c0 + c1) + (c2 + c3);
}

__device__ void scan_body(
    int b, int j,
    const float* __restrict__ trans,
    const int* __restrict__ target32,
    float* __restrict__ loss)
{
    const bool act = (j < L_);
    const int jc = min(j, 30);
    const float* eb = g_eos + (size_t)b * T_ * L_;

    // dtype detection: int64 target (LE) has zero high words at odd positions
    bool is64 = true;
#pragma unroll
    for (int qd = 0; qd < 64; qd++) is64 &= (__ldg(&target32[2 * qd + 1]) == 0);
    const int tstride = is64 ? 2 : 1;

    // forward column-gather sources
    const bool lightF = (j < 28) && (((j & 3) == 1) || ((j & 3) == 2));
    const int f0 = lightF ? (j & ~3) : 2;
    const int f1 = f0 + 1;

    float wF[16];
    {
        int src[16];
        src[0] = f0; src[1] = f1;
#pragma unroll
        for (int k = 1; k < 7; k++) { src[2*k] = 4*k + 2; src[2*k+1] = 4*k + 3; }
        src[14] = 28; src[15] = 29;
#pragma unroll
        for (int k = 0; k < 16; k++)
            wF[k] = act ? __expf(__ldg(&trans[src[k] * L_ + j])) : 0.f;
    }

    // backward row-gather sources
    int b0, b1;
    if (j < 28 && (j & 3) == 0)      { b0 = j + 1; b1 = j + 2; }
    else if (j < 28 && (j & 3) == 1) { b0 = j;     b1 = j + 1; }
    else if (j == 29)                { b0 = 29;    b1 = 30;    }
    else                             { b0 = 0;     b1 = 3;     }

    float wB[16];
    {
        int src[16];
        src[0] = b0; src[1] = b1;
        src[2] = 4;  src[3] = 7;  src[4] = 8;  src[5] = 11;
        src[6] = 12; src[7] = 15; src[8] = 16; src[9] = 19;
        src[10] = 20; src[11] = 23; src[12] = 24; src[13] = 27;
        src[14] = 28; src[15] = 29;
#pragma unroll
        for (int k = 0; k < 16; k++)
            wB[k] = act ? __expf(__ldg(&trans[jc * L_ + src[k]])) : 0.f;
    }

    float p = act ? __expf(__ldg(&trans[IDX_BOS * L_ + j])) * __ldg(&eb[j]) : 0.f;
    float v = act ? __expf(__ldg(&trans[jc * L_ + IDX_EOS])) : 0.f;
    int esF = 0, esB = 0;

    float e0F[8], e1F[8], e0B[8], e1B[8];
#pragma unroll
    for (int u = 0; u < 7; u++) e0F[u] = act ? eb[(1 + u) * L_ + j] : 0.f;
#pragma unroll
    for (int u = 0; u < 8; u++) {
        e0B[u] = act ? eb[(511 - u) * L_ + j] : 0.f;
        e1F[u] = act ? eb[(8 + u) * L_ + j] : 0.f;
        e1B[u] = act ? eb[(503 - u) * L_ + j] : 0.f;
    }

    stepB(v, b0, b1, wB, e0B[0]);
#pragma unroll
    for (int u = 0; u < 7; u++)
        stepFB(p, v, f0, f1, b0, b1, wF, wB, e0F[u], e0B[u + 1]);
    {
        unsigned mF = __reduce_max_sync(0xffffffffu, __float_as_uint(p));
        unsigned mB = __reduce_max_sync(0xffffffffu, __float_as_uint(v));
        int eF = (int)(mF >> 23), eB = (int)(mB >> 23);
        p *= __uint_as_float((unsigned)(253 - eF) << 23);
        v *= __uint_as_float((unsigned)(253 - eB) << 23);
        esF += eF - 126; esB += eB - 126;
    }

#pragma unroll 1
    for (int o = 1; o < 32; o++) {
#pragma unroll
        for (int u = 0; u < 8; u++) { e0F[u] = e1F[u]; e0B[u] = e1B[u]; }
        if (o < 31) {
            const int tf = 8 * (o + 1);
            const int tbk = 503 - 8 * o;
#pragma unroll
            for (int u = 0; u < 8; u++) {
                e1F[u] = act ? eb[(tf + u) * L_ + j] : 0.f;
                e1B[u] = act ? eb[(tbk - u) * L_ + j] : 0.f;
            }
        }
#pragma unroll
        for (int u = 0; u < 8; u++)
            stepFB(p, v, f0, f1, b0, b1, wF, wB, e0F[u], e0B[u]);
        unsigned mF = __reduce_max_sync(0xffffffffu, __float_as_uint(p));
        unsigned mB = __reduce_max_sync(0xffffffffu, __float_as_uint(v));
        int eF = (int)(mF >> 23), eB = (int)(mB >> 23);
        p *= __uint_as_float((unsigned)(253 - eF) << 23);
        v *= __uint_as_float((unsigned)(253 - eB) << 23);
        esF += eF - 126; esB += eB - 126;
    }

    // target energy
    const size_t tb = (size_t)b * T_;
    float ts = 0.f;
    for (int t = j; t < T_; t += 32) {
        int tgt  = __ldg(&target32[(tb + t) * tstride]);
        int prev = (t == 0) ? IDX_BOS : __ldg(&target32[(tb + t - 1) * tstride]);
        tgt  = min(max(tgt,  0), L_ - 1);
        prev = min(max(prev, 0), L_ - 1);
        ts += __ldg(&trans[prev * L_ + tgt]) + __ldg(&g_outs[(tb + t) * L_ + tgt]);
    }
#pragma unroll
    for (int s = 16; s; s >>= 1) ts += __shfl_xor_sync(0xffffffffu, ts, s);

    float z = p * v;
#pragma unroll
    for (int s = 16; s; s >>= 1) z += __shfl_xor_sync(0xffffffffu, z, s);

    if (j == 0) {
        const float LN2 = 0.6931471805599453f;
        loss[b] = (float)(esF + esB) * LN2 + __logf(z) - ts;
    }
}

// ---------------------------------------------------------------------------
// Kernel 2: fused scan (blocks 0..63, warp 0 only) + energy write
// (blocks 64..64+1023) — byte-identical to R12/R13 (measured good).
// ---------------------------------------------------------------------------
#define SCANB 64
#define ENERB 1024
#define NGRP  (NTOK / 4)   // 8192 = 1024 * 8

__global__ __launch_bounds__(256) void fused2(
    const float* __restrict__ trans,
    const int* __restrict__ target32,
    float* __restrict__ loss,
    float* __restrict__ energy)
{
    if (blockIdx.x < SCANB) {
        if (threadIdx.x < 32)
            scan_body(blockIdx.x, threadIdx.x, trans, target32, loss);
        return;
    }

    __shared__ float strans[LL_];
    const int tid = threadIdx.x;
    for (int i = tid; i < LL_; i += 256) strans[i] = __ldg(&trans[i]);
    __syncthreads();

    int pr0[4], pko[4];
#pragma unroll
    for (int s = 0; s < 4; s++) {
        int v  = tid + 256 * s;
        if (v > 960) { pr0[s] = 0; pko[s] = 0; continue; }
        int ff = 4 * v;
        int t0 = ff / 961;
        pr0[s] = ff - t0 * 961;
        int oj = 0;
#pragma unroll
        for (int u = 0; u < 4; u++) {
            int fu = ff + u;
            int tl = fu / 961;
            int r  = fu - tl * 961;
            int j  = r % 31;
            oj |= ((tl * 31 + j) & 255) << (8 * u);
        }
        pko[s] = oj;
    }
    const bool has3 = (tid + 768 <= 960);

    float4* e4 = (float4*)energy;
    int g = (int)blockIdx.x - SCANB;
#pragma unroll 1
    for (int it = 0; it < NGRP / ENERB; it++, g += ENERB) {
        const float* ob = g_outs + (size_t)g * 124;   // 4 tokens * 31
        const size_t base4 = (size_t)g * 961;
#pragma unroll
        for (int s = 0; s < 4; s++) {
            if (s == 3 && !has3) break;
            int v = tid + 256 * s;
            int r = pr0[s], oj = pko[s];
            float4 o;
            o.x = strans[r] + __ldg(&ob[oj & 127]);
            int r1 = r + 1; if (r1 >= 961) r1 -= 961;
            o.y = strans[r1] + __ldg(&ob[(oj >> 8) & 127]);
            int r2 = r + 2; if (r2 >= 961) r2 -= 961;
            o.z = strans[r2] + __ldg(&ob[(oj >> 16) & 127]);
            int r3 = r + 3; if (r3 >= 961) r3 -= 961;
            o.w = strans[r3] + __ldg(&ob[(oj >> 24) & 127]);
            e4[base4 + v] = o;
        }
    }
}

// ---------------------------------------------------------------------------
extern "C" void kernel_launch(void* const* d_in, const int* in_sizes, int n_in,
                              void* d_out, int out_size)
{
    const float* input   = (const float*)d_in[0];
    const int*   target  = (const int*)d_in[1];   // int32 or int64 (auto-detected)
    const float* mask    = (const float*)d_in[2];
    const float* state_w = (const float*)d_in[3];
    const float* state_b = (const float*)d_in[4];
    const float* trans   = (const float*)d_in[5];

    float* out    = (float*)d_out;
    float* loss   = out;            // 64 floats
    float* energy = out + B_;       // B*T*31*31 floats (offset 256B, 16B aligned)

    prep_w<<<60, 256>>>(state_w);
    gemm_kernel<<<NTOK / 64, 256>>>(input, state_b, mask);
    fused2<<<SCANB + ENERB, 256>>>(trans, target, loss, energy);
}

// round 17
// speedup vs baseline: 1.4490x; 1.2661x over previous
#include <cuda_runtime.h>
#include <cuda_fp16.h>
#include <cstdint>

// Shapes (fixed by the problem)
#define B_  64
#define T_  512
#define D_  768
#define L_  31
#define LL_ 961
#define NTOK (B_*T_)      // 32768
#define IDX_EOS 29
#define IDX_BOS 30

// Scratch (static __device__, no allocation)
__device__ float g_outs[NTOK * L_];   // out_s (post bias + mask adjust)
__device__ float g_eos [NTOK * L_];   // exp(out_s)
// packed f16x2 weight pairs (k-adjacent), pre-shuffled to the smem layout:
// chunk c (24 chunks of 32 k), word (kp 0..15, n 0..31) at
//   c*640 + kp*40 + (n&7)*4 + (n>>3)     [words 32..39 of each kp row = pad]
// values prescaled by 4096 (exact power of 2).
__device__ __align__(16) unsigned g_wph[24 * 640];
__device__ __align__(16) unsigned g_wpl[24 * 640];

__device__ __forceinline__ void mma16(float& c0, float& c1, float& c2, float& c3,
    unsigned a0, unsigned a1, unsigned a2, unsigned a3, unsigned b0, unsigned b1)
{
    asm("mma.sync.aligned.m16n8k16.row.col.f32.f16.f16.f32 "
        "{%0,%1,%2,%3}, {%4,%5,%6,%7}, {%8,%9}, {%0,%1,%2,%3};"
        : "+f"(c0), "+f"(c1), "+f"(c2), "+f"(c3)
        : "r"(a0), "r"(a1), "r"(a2), "r"(a3), "r"(b0), "r"(b1));
}

// split a float2 (scaled by 16) into f16x2 hi + f16x2 lo
__device__ __forceinline__ void split16(float2 f, unsigned& h, unsigned& l)
{
    float sx = f.x * 16.f, sy = f.y * 16.f;
    __half2 hh = __floats2half2_rn(sx, sy);
    float2 hf = __half22float2(hh);
    __half2 ll = __floats2half2_rn(sx - hf.x, sy - hf.y);
    h = *(unsigned*)&hh;
    l = *(unsigned*)&ll;
}

__device__ __forceinline__ unsigned s2u(const void* p) {
    return (unsigned)__cvta_generic_to_shared(p);
}
__device__ __forceinline__ void cp16(unsigned dst, const void* src) {
    asm volatile("cp.async.cg.shared.global [%0], [%1], 16;"
                 :: "r"(dst), "l"(src));
}

// ---------------------------------------------------------------------------
// Kernel 0: pack state_w into f16 hi/lo pairs, prescaled x4096, shuffled layout.
// ---------------------------------------------------------------------------
__global__ __launch_bounds__(256) void prep_w(const float* __restrict__ w)
{
    int i = blockIdx.x * 256 + threadIdx.x;
    if (i >= 24 * 640) return;
    int c  = i / 640, r = i - c * 640;
    int kp = r / 40,  wd = r - kp * 40;
    unsigned hi = 0, lo = 0;
    if (wd < 32) {
        int t4 = wd & 3, g = wd >> 2;
        int n  = t4 * 8 + g;
        int k0 = c * 32 + kp * 2;
        float v0 = (n < L_) ? __ldg(&w[n * D_ + k0])     * 4096.f : 0.f;
        float v1 = (n < L_) ? __ldg(&w[n * D_ + k0 + 1]) * 4096.f : 0.f;
        __half2 h = __floats2half2_rn(v0, v1);
        float2 hf = __half22float2(h);
        __half2 l = __floats2half2_rn(v0 - hf.x, v1 - hf.y);
        hi = *(unsigned*)&h;
        lo = *(unsigned*)&l;
    }
    g_wph[i] = hi;
    g_wpl[i] = lo;
}

// ---------------------------------------------------------------------------
// Kernel 1: f16 double-split GEMM (3 passes: hh, hl, lh) -> g_outs, g_eos.
// R13 structure (128 threads, 4 warps, 64x32 tile, k-chunk 32) with a
// 3-stage cp.async pipeline: stage ch+2 issued while computing ch,
// ONE __syncthreads per chunk, no register staging.
// FIX vs R16: B loader covers all 160 uint4s with 128 threads
// (tid loads element tid; tid<32 also loads tid+128).
// Static smem: 3*(64*40*4 + 2*640*4) = 46080 B (< 48KB).
// ---------------------------------------------------------------------------
#define CH  32
#define NCH (D_/CH)   // 24

__global__ __launch_bounds__(128) void gemm_kernel(
    const float* __restrict__ input,
    const float* __restrict__ state_b,
    const float* __restrict__ mask)
{
    __shared__ __align__(16) float    sA [3][64 * 40];
    __shared__ __align__(16) unsigned sBh[3][640];
    __shared__ __align__(16) unsigned sBl[3][640];

    const int tid  = threadIdx.x;
    const int lane = tid & 31, warp = tid >> 5;
    const int g    = lane >> 2, q = lane & 3;
    const int tokbase = blockIdx.x * 64;

    float c[4][4];
#pragma unroll
    for (int t4 = 0; t4 < 4; t4++)
#pragma unroll
        for (int u = 0; u < 4; u++) c[t4][u] = 0.f;

    auto issue = [&](int ch) {
        const int k0  = ch * CH;
        const int buf = ch % 3;
        float* A = sA[buf];
#pragma unroll
        for (int i = 0; i < 4; i++) {
            int idx = tid + 128 * i; int row = idx >> 3, c4 = idx & 7;
            cp16(s2u(A + row * 40 + c4 * 4),
                 input + (size_t)(tokbase + row) * D_ + k0 + c4 * 4);
        }
        const uint4* gh = (const uint4*)(g_wph + ch * 640);
        const uint4* gl = (const uint4*)(g_wpl + ch * 640);
        cp16(s2u(sBh[buf] + tid * 4), gh + tid);
        cp16(s2u(sBl[buf] + tid * 4), gl + tid);
        if (tid < 32) {
            cp16(s2u(sBh[buf] + (tid + 128) * 4), gh + tid + 128);
            cp16(s2u(sBl[buf] + (tid + 128) * 4), gl + tid + 128);
        }
    };

    issue(0);
    asm volatile("cp.async.commit_group;" ::: "memory");
    issue(1);
    asm volatile("cp.async.commit_group;" ::: "memory");

    const int ar = warp * 16 + g;
    for (int ch = 0; ch < NCH; ch++) {
        asm volatile("cp.async.wait_group 1;" ::: "memory");
        __syncthreads();                        // stage ch visible; compute(ch-1) done
        if (ch + 2 < NCH) issue(ch + 2);        // overwrites buf (ch-1)%3 — safe
        asm volatile("cp.async.commit_group;" ::: "memory");

        const int buf = ch % 3;
        const float*    A  = sA [buf];
        const unsigned* Bh = sBh[buf];
        const unsigned* Bl = sBl[buf];

#pragma unroll
        for (int kk = 0; kk < 2; kk++) {
            const int K0 = kk * 16 + 2 * q;
            float2 f00 = *(const float2*)&A[ar * 40 + K0];
            float2 f01 = *(const float2*)&A[(ar + 8) * 40 + K0];
            float2 f10 = *(const float2*)&A[ar * 40 + K0 + 8];
            float2 f11 = *(const float2*)&A[(ar + 8) * 40 + K0 + 8];

            // a-frag order (ldmatrix-canonical): a0=(g,klo) a1=(g+8,klo)
            //                                    a2=(g,khi) a3=(g+8,khi)
            unsigned ah0, ah1, ah2, ah3, al0, al1, al2, al3;
            split16(f00, ah0, al0);
            split16(f01, ah1, al1);
            split16(f10, ah2, al2);
            split16(f11, ah3, al3);

            const int b0i = (kk * 8 + q) * 40 + g * 4;
            uint4 B0h = *(const uint4*)&Bh[b0i];
            uint4 B1h = *(const uint4*)&Bh[b0i + 160];   // kp+4 rows
            uint4 B0l = *(const uint4*)&Bl[b0i];
            uint4 B1l = *(const uint4*)&Bl[b0i + 160];
            unsigned b0h[4] = {B0h.x, B0h.y, B0h.z, B0h.w};
            unsigned b1h[4] = {B1h.x, B1h.y, B1h.z, B1h.w};
            unsigned b0l[4] = {B0l.x, B0l.y, B0l.z, B0l.w};
            unsigned b1l[4] = {B1l.x, B1l.y, B1l.z, B1l.w};

#pragma unroll
            for (int t4 = 0; t4 < 4; t4++) {
                mma16(c[t4][0], c[t4][1], c[t4][2], c[t4][3],
                      ah0, ah1, ah2, ah3, b0h[t4], b1h[t4]);   // hh
                mma16(c[t4][0], c[t4][1], c[t4][2], c[t4][3],
                      ah0, ah1, ah2, ah3, b0l[t4], b1l[t4]);   // hl
                mma16(c[t4][0], c[t4][1], c[t4][2], c[t4][3],
                      al0, al1, al2, al3, b0h[t4], b1h[t4]);   // lh
            }
        }
    }
    __syncthreads();

    // ---- epilogue: outs tile to smem (overlay on sA[0], dead now) ----
    const float INV = 1.52587890625e-05f;   // 2^-16, exact
    float* outs = sA[0];                    // 64 x 32, pitch 32
    {
        const int r0 = warp * 16 + g;
        const int jb = 2 * q;
        const float mk0 = __ldg(&mask[tokbase + r0]);
        const float mk1 = __ldg(&mask[tokbase + r0 + 8]);
#pragma unroll
        for (int t4 = 0; t4 < 4; t4++) {
            const int j0 = t4 * 8 + jb;
            float bb = __ldg(&state_b[j0]);
            float v00 = c[t4][0] * INV + bb, v10 = c[t4][2] * INV + bb;
            if (j0 == IDX_EOS) { v00 += (mk0 == 0.f) ? 2e4f : 0.f;
                                 v10 += (mk1 == 0.f) ? 2e4f : 0.f; }
            outs[r0 * 32 + j0]       = v00;
            outs[(r0 + 8) * 32 + j0] = v10;
            const int j1 = j0 + 1;
            if (j1 < L_) {
                float bb1 = __ldg(&state_b[j1]);
                float v01 = c[t4][1] * INV + bb1, v11 = c[t4][3] * INV + bb1;
                if (j1 == IDX_EOS) { v01 += (mk0 == 0.f) ? 2e4f : 0.f;
                                     v11 += (mk1 == 0.f) ? 2e4f : 0.f; }
                outs[r0 * 32 + j1]       = v01;
                outs[(r0 + 8) * 32 + j1] = v11;
            }
        }
    }
    __syncthreads();

    // ---- g_outs / g_eos ----
    for (int i = tid; i < 64 * L_; i += 128) {
        int tok = i / L_;
        int j   = i - tok * L_;
        float v = outs[tok * 32 + j];
        size_t gi = (size_t)(tokbase + tok) * L_ + j;
        g_outs[gi] = v;
        g_eos [gi] = __expf(v);
    }
}

// ---------------------------------------------------------------------------
// Scan pieces (R11/R12, measured good): forward/backward split, one warp/batch.
// ---------------------------------------------------------------------------
#define SHF(x, s) __shfl_sync(0xffffffffu, x, s)

__device__ __forceinline__ void stepFB(float& p, float& v,
    int f0, int f1, int b0, int b1,
    const float (&wF)[16], const float (&wB)[16], float eF, float eB)
{
    float g = eB * v;
    float a0 = wF[0] * SHF(p, f0);
    float a1 = wF[1] * SHF(p, f1);
    float c0 = wB[0] * SHF(g, b0);
    float c1 = wB[1] * SHF(g, b1);
    float a2 = wF[2] * SHF(p, 6);
    float a3 = wF[3] * SHF(p, 7);
    float c2 = wB[2] * SHF(g, 4);
    float c3 = wB[3] * SHF(g, 7);
    a0 = fmaf(wF[4],  SHF(p, 10), a0);  c0 = fmaf(wB[4],  SHF(g, 8),  c0);
    a1 = fmaf(wF[5],  SHF(p, 11), a1);  c1 = fmaf(wB[5],  SHF(g, 11), c1);
    a2 = fmaf(wF[6],  SHF(p, 14), a2);  c2 = fmaf(wB[6],  SHF(g, 12), c2);
    a3 = fmaf(wF[7],  SHF(p, 15), a3);  c3 = fmaf(wB[7],  SHF(g, 15), c3);
    a0 = fmaf(wF[8],  SHF(p, 18), a0);  c0 = fmaf(wB[8],  SHF(g, 16), c0);
    a1 = fmaf(wF[9],  SHF(p, 19), a1);  c1 = fmaf(wB[9],  SHF(g, 19), c1);
    a2 = fmaf(wF[10], SHF(p, 22), a2);  c2 = fmaf(wB[10], SHF(g, 20), c2);
    a3 = fmaf(wF[11], SHF(p, 23), a3);  c3 = fmaf(wB[11], SHF(g, 23), c3);
    a0 = fmaf(wF[12], SHF(p, 26), a0);  c0 = fmaf(wB[12], SHF(g, 24), c0);
    a1 = fmaf(wF[13], SHF(p, 27), a1);  c1 = fmaf(wB[13], SHF(g, 27), c1);
    a2 = fmaf(wF[14], SHF(p, 28), a2);  c2 = fmaf(wB[14], SHF(g, 28), c2);
    a3 = fmaf(wF[15], SHF(p, 29), a3);  c3 = fmaf(wB[15], SHF(g, 29), c3);
    p = ((a0 + a1) + (a2 + a3)) * eF;
    v = (c0 + c1) + (c2 + c3);
}

__device__ __forceinline__ void stepB(float& v, int b0, int b1,
                                      const float (&wB)[16], float eB)
{
    float g = eB * v;
    float c0 = wB[0] * SHF(g, b0);
    float c1 = wB[1] * SHF(g, b1);
    float c2 = wB[2] * SHF(g, 4);
    float c3 = wB[3] * SHF(g, 7);
    c0 = fmaf(wB[4],  SHF(g, 8),  c0);
    c1 = fmaf(wB[5],  SHF(g, 11), c1);
    c2 = fmaf(wB[6],  SHF(g, 12), c2);
    c3 = fmaf(wB[7],  SHF(g, 15), c3);
    c0 = fmaf(wB[8],  SHF(g, 16), c0);
    c1 = fmaf(wB[9],  SHF(g, 19), c1);
    c2 = fmaf(wB[10], SHF(g, 20), c2);
    c3 = fmaf(wB[11], SHF(g, 23), c3);
    c0 = fmaf(wB[12], SHF(g, 24), c0);
    c1 = fmaf(wB[13], SHF(g, 27), c1);
    c2 = fmaf(wB[14], SHF(g, 28), c2);
    c3 = fmaf(wB[15], SHF(g, 29), c3);
    v = (c0 + c1) + (c2 + c3);
}

__device__ void scan_body(
    int b, int j,
    const float* __restrict__ trans,
    const int* __restrict__ target32,
    float* __restrict__ loss)
{
    const bool act = (j < L_);
    const int jc = min(j, 30);
    const float* eb = g_eos + (size_t)b * T_ * L_;

    // dtype detection: int64 target (LE) has zero high words at odd positions
    bool is64 = true;
#pragma unroll
    for (int qd = 0; qd < 64; qd++) is64 &= (__ldg(&target32[2 * qd + 1]) == 0);
    const int tstride = is64 ? 2 : 1;

    // forward column-gather sources
    const bool lightF = (j < 28) && (((j & 3) == 1) || ((j & 3) == 2));
    const int f0 = lightF ? (j & ~3) : 2;
    const int f1 = f0 + 1;

    float wF[16];
    {
        int src[16];
        src[0] = f0; src[1] = f1;
#pragma unroll
        for (int k = 1; k < 7; k++) { src[2*k] = 4*k + 2; src[2*k+1] = 4*k + 3; }
        src[14] = 28; src[15] = 29;
#pragma unroll
        for (int k = 0; k < 16; k++)
            wF[k] = act ? __expf(__ldg(&trans[src[k] * L_ + j])) : 0.f;
    }

    // backward row-gather sources
    int b0, b1;
    if (j < 28 && (j & 3) == 0)      { b0 = j + 1; b1 = j + 2; }
    else if (j < 28 && (j & 3) == 1) { b0 = j;     b1 = j + 1; }
    else if (j == 29)                { b0 = 29;    b1 = 30;    }
    else                             { b0 = 0;     b1 = 3;     }

    float wB[16];
    {
        int src[16];
        src[0] = b0; src[1] = b1;
        src[2] = 4;  src[3] = 7;  src[4] = 8;  src[5] = 11;
        src[6] = 12; src[7] = 15; src[8] = 16; src[9] = 19;
        src[10] = 20; src[11] = 23; src[12] = 24; src[13] = 27;
        src[14] = 28; src[15] = 29;
#pragma unroll
        for (int k = 0; k < 16; k++)
            wB[k] = act ? __expf(__ldg(&trans[jc * L_ + src[k]])) : 0.f;
    }

    float p = act ? __expf(__ldg(&trans[IDX_BOS * L_ + j])) * __ldg(&eb[j]) : 0.f;
    float v = act ? __expf(__ldg(&trans[jc * L_ + IDX_EOS])) : 0.f;
    int esF = 0, esB = 0;

    float e0F[8], e1F[8], e0B[8], e1B[8];
#pragma unroll
    for (int u = 0; u < 7; u++) e0F[u] = act ? eb[(1 + u) * L_ + j] : 0.f;
#pragma unroll
    for (int u = 0; u < 8; u++) {
        e0B[u] = act ? eb[(511 - u) * L_ + j] : 0.f;
        e1F[u] = act ? eb[(8 + u) * L_ + j] : 0.f;
        e1B[u] = act ? eb[(503 - u) * L_ + j] : 0.f;
    }

    stepB(v, b0, b1, wB, e0B[0]);
#pragma unroll
    for (int u = 0; u < 7; u++)
        stepFB(p, v, f0, f1, b0, b1, wF, wB, e0F[u], e0B[u + 1]);
    {
        unsigned mF = __reduce_max_sync(0xffffffffu, __float_as_uint(p));
        unsigned mB = __reduce_max_sync(0xffffffffu, __float_as_uint(v));
        int eF = (int)(mF >> 23), eB = (int)(mB >> 23);
        p *= __uint_as_float((unsigned)(253 - eF) << 23);
        v *= __uint_as_float((unsigned)(253 - eB) << 23);
        esF += eF - 126; esB += eB - 126;
    }

#pragma unroll 1
    for (int o = 1; o < 32; o++) {
#pragma unroll
        for (int u = 0; u < 8; u++) { e0F[u] = e1F[u]; e0B[u] = e1B[u]; }
        if (o < 31) {
            const int tf = 8 * (o + 1);
            const int tbk = 503 - 8 * o;
#pragma unroll
            for (int u = 0; u < 8; u++) {
                e1F[u] = act ? eb[(tf + u) * L_ + j] : 0.f;
                e1B[u] = act ? eb[(tbk - u) * L_ + j] : 0.f;
            }
        }
#pragma unroll
        for (int u = 0; u < 8; u++)
            stepFB(p, v, f0, f1, b0, b1, wF, wB, e0F[u], e0B[u]);
        unsigned mF = __reduce_max_sync(0xffffffffu, __float_as_uint(p));
        unsigned mB = __reduce_max_sync(0xffffffffu, __float_as_uint(v));
        int eF = (int)(mF >> 23), eB = (int)(mB >> 23);
        p *= __uint_as_float((unsigned)(253 - eF) << 23);
        v *= __uint_as_float((unsigned)(253 - eB) << 23);
        esF += eF - 126; esB += eB - 126;
    }

    // target energy
    const size_t tb = (size_t)b * T_;
    float ts = 0.f;
    for (int t = j; t < T_; t += 32) {
        int tgt  = __ldg(&target32[(tb + t) * tstride]);
        int prev = (t == 0) ? IDX_BOS : __ldg(&target32[(tb + t - 1) * tstride]);
        tgt  = min(max(tgt,  0), L_ - 1);
        prev = min(max(prev, 0), L_ - 1);
        ts += __ldg(&trans[prev * L_ + tgt]) + __ldg(&g_outs[(tb + t) * L_ + tgt]);
    }
#pragma unroll
    for (int s = 16; s; s >>= 1) ts += __shfl_xor_sync(0xffffffffu, ts, s);

    float z = p * v;
#pragma unroll
    for (int s = 16; s; s >>= 1) z += __shfl_xor_sync(0xffffffffu, z, s);

    if (j == 0) {
        const float LN2 = 0.6931471805599453f;
        loss[b] = (float)(esF + esB) * LN2 + __logf(z) - ts;
    }
}

// ---------------------------------------------------------------------------
// Kernel 2: fused scan (blocks 0..63, warp 0 only) + energy write
// (blocks 64..64+1023) — byte-identical to R12/R13 (measured good).
// ---------------------------------------------------------------------------
#define SCANB 64
#define ENERB 1024
#define NGRP  (NTOK / 4)   // 8192 = 1024 * 8

__global__ __launch_bounds__(256) void fused2(
    const float* __restrict__ trans,
    const int* __restrict__ target32,
    float* __restrict__ loss,
    float* __restrict__ energy)
{
    if (blockIdx.x < SCANB) {
        if (threadIdx.x < 32)
            scan_body(blockIdx.x, threadIdx.x, trans, target32, loss);
        return;
    }

    __shared__ float strans[LL_];
    const int tid = threadIdx.x;
    for (int i = tid; i < LL_; i += 256) strans[i] = __ldg(&trans[i]);
    __syncthreads();

    int pr0[4], pko[4];
#pragma unroll
    for (int s = 0; s < 4; s++) {
        int v  = tid + 256 * s;
        if (v > 960) { pr0[s] = 0; pko[s] = 0; continue; }
        int ff = 4 * v;
        int t0 = ff / 961;
        pr0[s] = ff - t0 * 961;
        int oj = 0;
#pragma unroll
        for (int u = 0; u < 4; u++) {
            int fu = ff + u;
            int tl = fu / 961;
            int r  = fu - tl * 961;
            int j  = r % 31;
            oj |= ((tl * 31 + j) & 255) << (8 * u);
        }
        pko[s] = oj;
    }
    const bool has3 = (tid + 768 <= 960);

    float4* e4 = (float4*)energy;
    int g = (int)blockIdx.x - SCANB;
#pragma unroll 1
    for (int it = 0; it < NGRP / ENERB; it++, g += ENERB) {
        const float* ob = g_outs + (size_t)g * 124;   // 4 tokens * 31
        const size_t base4 = (size_t)g * 961;
#pragma unroll
        for (int s = 0; s < 4; s++) {
            if (s == 3 && !has3) break;
            int v = tid + 256 * s;
            int r = pr0[s], oj = pko[s];
            float4 o;
            o.x = strans[r] + __ldg(&ob[oj & 127]);
            int r1 = r + 1; if (r1 >= 961) r1 -= 961;
            o.y = strans[r1] + __ldg(&ob[(oj >> 8) & 127]);
            int r2 = r + 2; if (r2 >= 961) r2 -= 961;
            o.z = strans[r2] + __ldg(&ob[(oj >> 16) & 127]);
            int r3 = r + 3; if (r3 >= 961) r3 -= 961;
            o.w = strans[r3] + __ldg(&ob[(oj >> 24) & 127]);
            e4[base4 + v] = o;
        }
    }
}

// ---------------------------------------------------------------------------
extern "C" void kernel_launch(void* const* d_in, const int* in_sizes, int n_in,
                              void* d_out, int out_size)
{
    const float* input   = (const float*)d_in[0];
    const int*   target  = (const int*)d_in[1];   // int32 or int64 (auto-detected)
    const float* mask    = (const float*)d_in[2];
    const float* state_w = (const float*)d_in[3];
    const float* state_b = (const float*)d_in[4];
    const float* trans   = (const float*)d_in[5];

    float* out    = (float*)d_out;
    float* loss   = out;            // 64 floats
    float* energy = out + B_;       // B*T*31*31 floats (offset 256B, 16B aligned)

    prep_w<<<60, 256>>>(state_w);
    gemm_kernel<<<NTOK / 64, 128>>>(input, state_b, mask);
    fused2<<<SCANB + ENERB, 256>>>(trans, target, loss, energy);
}